// round 3
// baseline (speedup 1.0000x reference)
#include <cuda_runtime.h>
#include <cstdint>

#define NN   500000
#define EE   4000000
#define FIN  24
#define HH   64
#define KC   6
#define OD   6
#define EPSBN 1e-5f
#define NB   ((NN + 1023) / 1024)   // scan blocks = 489

// ---------------- static scratch ----------------
__device__ int    g_deg[NN];
__device__ float  g_dis[NN];
__device__ int    g_rowptr[NN + 1];
__device__ int    g_cur[NN];
__device__ int    g_bsum[NB];
__device__ int    g_boff[NB];
__device__ float2 g_csr[EE];                 // {src_as_float_bits, weight} sorted by dst
__device__ float  g_T[5][NN * FIN];          // T1..T5 (T0 == x input)
__device__ float  g_h[(size_t)NN * HH];
__device__ float  g_sum[HH];
__device__ float  g_sumsq[HH];
__device__ float  g_scale[HH];
__device__ float  g_shift[HH];

// ---------------- helpers ----------------
__device__ __forceinline__ unsigned long long pack2(float lo, float hi) {
    unsigned long long r;
    asm("mov.b64 %0, {%1, %2};" : "=l"(r) : "f"(lo), "f"(hi));
    return r;
}
__device__ __forceinline__ void unpack2(unsigned long long v, float& lo, float& hi) {
    asm("mov.b64 {%0, %1}, %2;" : "=f"(lo), "=f"(hi) : "l"(v));
}
__device__ __forceinline__ void ffma2(unsigned long long& d, unsigned long long a,
                                      unsigned long long b) {
    asm("fma.rn.f32x2 %0, %1, %2, %0;" : "+l"(d) : "l"(a), "l"(b));
}

// ---------------- kernels ----------------
__global__ void k_zero() {
    int i = blockIdx.x * blockDim.x + threadIdx.x;
    if (i < NN) g_deg[i] = 0;
    if (i < HH) { g_sum[i] = 0.f; g_sumsq[i] = 0.f; }
}

__global__ void k_deg(const int4* __restrict__ col4) {
    int i = blockIdx.x * blockDim.x + threadIdx.x;
    if (i >= EE / 4) return;
    int4 c = __ldg(col4 + i);
    atomicAdd(&g_deg[c.x], 1);
    atomicAdd(&g_deg[c.y], 1);
    atomicAdd(&g_deg[c.z], 1);
    atomicAdd(&g_deg[c.w], 1);
}

__global__ void k_dis() {
    int i = blockIdx.x * blockDim.x + threadIdx.x;
    if (i < NN) {
        int d = g_deg[i];
        g_dis[i] = (d > 0) ? rsqrtf((float)d) : 0.f;
    }
}

// ---- two-level exclusive scan of g_deg into g_rowptr ----
__global__ __launch_bounds__(1024) void k_scan1() {
    __shared__ int s[1024];
    int tid = threadIdx.x;
    int i = blockIdx.x * 1024 + tid;
    int v = (i < NN) ? g_deg[i] : 0;
    s[tid] = v;
    __syncthreads();
#pragma unroll
    for (int off = 1; off < 1024; off <<= 1) {
        int t = (tid >= off) ? s[tid - off] : 0;
        __syncthreads();
        s[tid] += t;
        __syncthreads();
    }
    if (i < NN) g_rowptr[i] = s[tid] - v;   // exclusive (partial, per-block)
    if (tid == 1023) g_bsum[blockIdx.x] = s[1023];
}

__global__ __launch_bounds__(512) void k_scan2() {
    __shared__ int s[512];
    int tid = threadIdx.x;
    int v = (tid < NB) ? g_bsum[tid] : 0;
    s[tid] = v;
    __syncthreads();
#pragma unroll
    for (int off = 1; off < 512; off <<= 1) {
        int t = (tid >= off) ? s[tid - off] : 0;
        __syncthreads();
        s[tid] += t;
        __syncthreads();
    }
    if (tid < NB) g_boff[tid] = s[tid] - v;
}

__global__ void k_scan3() {
    int i = blockIdx.x * blockDim.x + threadIdx.x;
    if (i < NN) {
        int rp = g_rowptr[i] + g_boff[i >> 10];
        g_rowptr[i] = rp;
        g_cur[i] = rp;
    }
    if (i == 0) g_rowptr[NN] = EE;
}

// scatter edges into CSR sorted by dst; weight computed inline
__global__ void k_scatter(const int* __restrict__ row, const int* __restrict__ col) {
    int e = blockIdx.x * blockDim.x + threadIdx.x;
    if (e >= EE) return;
    int r = __ldg(row + e);
    int c = __ldg(col + e);
    float w = -g_dis[r] * g_dis[c];
    int pos = atomicAdd(&g_cur[c], 1);
    g_csr[pos] = make_float2(__int_as_float(r), w);
}

// T_dst = scl * sum_{e in list(n)} w_e * src[row_e]  [- T_prev2]   (gather, no atomics)
// 2 threads per node, each handles 12 features (3 float4)
__global__ __launch_bounds__(256) void k_gather(int dsti, int prevI, int prev2I,
                                                const float* __restrict__ x,
                                                float scl, int do_sub) {
    int t = blockIdx.x * blockDim.x + threadIdx.x;
    int n = t >> 1;
    if (n >= NN) return;
    int h = t & 1;
    const float* src = (prevI < 0) ? x : g_T[prevI];

    int p  = g_rowptr[n];
    int p1 = g_rowptr[n + 1];

    float a0x=0,a0y=0,a0z=0,a0w=0, a1x=0,a1y=0,a1z=0,a1w=0, a2x=0,a2y=0,a2z=0,a2w=0;
    for (; p < p1; p++) {
        float2 ew = __ldg(&g_csr[p]);
        int r = __float_as_int(ew.x);
        float w = ew.y;
        const float4* v4 = (const float4*)(src + (size_t)r * FIN) + h * 3;
        float4 v0 = __ldg(v4 + 0);
        float4 v1 = __ldg(v4 + 1);
        float4 v2 = __ldg(v4 + 2);
        a0x += w * v0.x; a0y += w * v0.y; a0z += w * v0.z; a0w += w * v0.w;
        a1x += w * v1.x; a1y += w * v1.y; a1z += w * v1.z; a1w += w * v1.w;
        a2x += w * v2.x; a2y += w * v2.y; a2z += w * v2.z; a2w += w * v2.w;
    }

    float4 o0 = make_float4(scl*a0x, scl*a0y, scl*a0z, scl*a0w);
    float4 o1 = make_float4(scl*a1x, scl*a1y, scl*a1z, scl*a1w);
    float4 o2 = make_float4(scl*a2x, scl*a2y, scl*a2z, scl*a2w);
    if (do_sub) {
        const float4* pp = (const float4*)(((prev2I < 0) ? x : g_T[prev2I]) +
                                           (size_t)n * FIN) + h * 3;
        float4 q0 = __ldg(pp + 0), q1 = __ldg(pp + 1), q2 = __ldg(pp + 2);
        o0.x -= q0.x; o0.y -= q0.y; o0.z -= q0.z; o0.w -= q0.w;
        o1.x -= q1.x; o1.y -= q1.y; o1.z -= q1.z; o1.w -= q1.w;
        o2.x -= q2.x; o2.y -= q2.y; o2.z -= q2.z; o2.w -= q2.w;
    }
    float4* d4 = (float4*)(g_T[dsti] + (size_t)n * FIN) + h * 3;
    d4[0] = o0; d4[1] = o1; d4[2] = o2;
}

// h = [x|T1..T5] @ W[144,64] + b1 ; packed f32x2, 2 nodes/thread, H halves
__global__ __launch_bounds__(128) void k_gemm(const float* __restrict__ x,
                                              const float* __restrict__ W1,
                                              const float* __restrict__ b1) {
    __shared__ float sW[KC * FIN * HH];   // 36 KB
    __shared__ float sRs[4][HH];
    __shared__ float sRq[4][HH];

    int tid = threadIdx.x;
    for (int i = tid; i < KC * FIN * HH; i += 128) sW[i] = W1[i];
    __syncthreads();

    int half = tid & 1;
    int n0 = blockIdx.x * 128 + (tid >> 1) * 2;
    int n1 = n0 + 1;
    bool v0 = (n0 < NN), v1 = (n1 < NN);

    unsigned long long acc0[16], acc1[16];
#pragma unroll
    for (int j = 0; j < 16; j++) { acc0[j] = 0ull; acc1[j] = 0ull; }

#pragma unroll
    for (int k = 0; k < KC; k++) {
        const float* base = (k == 0 ? x : g_T[k - 1]);
        const float4* s40 = (const float4*)(base + (size_t)n0 * FIN);
        const float4* s41 = (const float4*)(base + (size_t)n1 * FIN);
#pragma unroll
        for (int i4 = 0; i4 < 6; i4++) {
            float4 a = v0 ? __ldg(s40 + i4) : make_float4(0.f, 0.f, 0.f, 0.f);
            float4 b = v1 ? __ldg(s41 + i4) : make_float4(0.f, 0.f, 0.f, 0.f);
            float av[4] = {a.x, a.y, a.z, a.w};
            float bv[4] = {b.x, b.y, b.z, b.w};
#pragma unroll
            for (int t = 0; t < 4; t++) {
                int i = i4 * 4 + t;
                unsigned long long pa = pack2(av[t], av[t]);
                unsigned long long pb = pack2(bv[t], bv[t]);
                const unsigned long long* wr =
                    (const unsigned long long*)&sW[(k * FIN + i) * HH + half * 32];
#pragma unroll
                for (int j = 0; j < 16; j++) {
                    unsigned long long wj = wr[j];
                    ffma2(acc0[j], pa, wj);
                    ffma2(acc1[j], pb, wj);
                }
            }
        }
    }

    float s[32], q[32];
#pragma unroll
    for (int j = 0; j < 16; j++) {
        float b0 = __ldg(&b1[half * 32 + 2 * j]);
        float b1v = __ldg(&b1[half * 32 + 2 * j + 1]);
        float a0, a1c, c0, c1;
        unpack2(acc0[j], a0, a1c);
        unpack2(acc1[j], c0, c1);
        a0 += b0; a1c += b1v; c0 += b0; c1 += b1v;
        s[2 * j]     = (v0 ? a0 : 0.f) + (v1 ? c0 : 0.f);
        s[2 * j + 1] = (v0 ? a1c : 0.f) + (v1 ? c1 : 0.f);
        q[2 * j]     = (v0 ? a0 * a0 : 0.f) + (v1 ? c0 * c0 : 0.f);
        q[2 * j + 1] = (v0 ? a1c * a1c : 0.f) + (v1 ? c1 * c1 : 0.f);
        if (v0) ((float2*)(g_h + (size_t)n0 * HH + half * 32))[j] = make_float2(a0, a1c);
        if (v1) ((float2*)(g_h + (size_t)n1 * HH + half * 32))[j] = make_float2(c0, c1);
    }

    int lane = tid & 31, wid = tid >> 5;
#pragma unroll
    for (int j = 0; j < 32; j++) {
        float sv = s[j], qv = q[j];
#pragma unroll
        for (int off = 2; off < 32; off <<= 1) {
            sv += __shfl_xor_sync(0xffffffffu, sv, off);
            qv += __shfl_xor_sync(0xffffffffu, qv, off);
        }
        if ((lane >> 1) == 0) {
            sRs[wid][(lane & 1) * 32 + j] = sv;
            sRq[wid][(lane & 1) * 32 + j] = qv;
        }
    }
    __syncthreads();
    if (tid < HH) {
        float a = sRs[0][tid] + sRs[1][tid] + sRs[2][tid] + sRs[3][tid];
        float b = sRq[0][tid] + sRq[1][tid] + sRq[2][tid] + sRq[3][tid];
        atomicAdd(&g_sum[tid], a);
        atomicAdd(&g_sumsq[tid], b);
    }
}

__global__ void k_bnparam(const float* __restrict__ gamma, const float* __restrict__ beta) {
    int j = threadIdx.x;
    if (j < HH) {
        float inv_n = 1.f / (float)NN;
        float mean = g_sum[j] * inv_n;
        float var  = g_sumsq[j] * inv_n - mean * mean;
        float rstd = rsqrtf(var + EPSBN);
        float sc = gamma[j] * rstd;
        g_scale[j] = sc;
        g_shift[j] = beta[j] - mean * sc;
    }
}

__global__ __launch_bounds__(256) void k_final(const float* __restrict__ Wmix,
                                               const float* __restrict__ bmix,
                                               float* __restrict__ out) {
    __shared__ float sWm[HH * OD];
    __shared__ float sSc[HH], sSh[HH], sB[OD];
    int tid = threadIdx.x;
    for (int i = tid; i < HH * OD; i += 256) sWm[i] = Wmix[i];
    if (tid < HH) { sSc[tid] = g_scale[tid]; sSh[tid] = g_shift[tid]; }
    if (tid < OD) sB[tid] = bmix[tid];
    __syncthreads();

    int n = blockIdx.x * 256 + tid;
    if (n >= NN) return;

    float o0 = sB[0], o1 = sB[1], o2 = sB[2], o3 = sB[3], o4 = sB[4], o5 = sB[5];
    const float4* hp = (const float4*)(g_h + (size_t)n * HH);
#pragma unroll
    for (int j4 = 0; j4 < 16; j4++) {
        float4 hv = hp[j4];
        float hv4[4] = {hv.x, hv.y, hv.z, hv.w};
#pragma unroll
        for (int t = 0; t < 4; t++) {
            int j = 4 * j4 + t;
            float val = fmaxf(hv4[t] * sSc[j] + sSh[j], 0.f);
            const float* wm = &sWm[j * OD];
            o0 += val * wm[0]; o1 += val * wm[1]; o2 += val * wm[2];
            o3 += val * wm[3]; o4 += val * wm[4]; o5 += val * wm[5];
        }
    }
    float* op = out + (size_t)n * OD;
    op[0] = o0; op[1] = o1; op[2] = o2; op[3] = o3; op[4] = o4; op[5] = o5;
}

// ---------------- launch ----------------
extern "C" void kernel_launch(void* const* d_in, const int* in_sizes, int n_in,
                              void* d_out, int out_size) {
    const float* x     = (const float*)d_in[0];
    const int*   ei    = (const int*)  d_in[1];
    const float* W1    = (const float*)d_in[2];
    const float* b1    = (const float*)d_in[3];
    const float* gamma = (const float*)d_in[4];
    const float* beta  = (const float*)d_in[5];
    const float* Wmix  = (const float*)d_in[6];
    const float* bmix  = (const float*)d_in[7];
    float* out = (float*)d_out;

    const int* row = ei;
    const int* col = ei + EE;

    const int TB = 256;
    int gN  = (NN + TB - 1) / TB;
    int gE  = (EE + TB - 1) / TB;
    int gE4 = (EE / 4 + TB - 1) / TB;
    int gG  = (2 * NN + TB - 1) / TB;

    k_zero<<<gN, TB>>>();
    k_deg<<<gE4, TB>>>((const int4*)col);
    k_dis<<<gN, TB>>>();
    k_scan1<<<NB, 1024>>>();
    k_scan2<<<1, 512>>>();
    k_scan3<<<gN, TB>>>();
    k_scatter<<<gE, TB>>>(row, col);

    // T1 = L_hat x
    k_gather<<<gG, TB>>>(0, -1, 0, x, 1.f, 0);
    // T2 = 2 L_hat T1 - x
    k_gather<<<gG, TB>>>(1, 0, -1, x, 2.f, 1);
    // T3 = 2 L_hat T2 - T1
    k_gather<<<gG, TB>>>(2, 1, 0, x, 2.f, 1);
    // T4 = 2 L_hat T3 - T2
    k_gather<<<gG, TB>>>(3, 2, 1, x, 2.f, 1);
    // T5 = 2 L_hat T4 - T3
    k_gather<<<gG, TB>>>(4, 3, 2, x, 2.f, 1);

    k_gemm<<<(NN + 127) / 128, 128>>>(x, W1, b1);
    k_bnparam<<<1, HH>>>(gamma, beta);
    k_final<<<gN, TB>>>(Wmix, bmix, out);
}

// round 4
// speedup vs baseline: 1.3827x; 1.3827x over previous
#include <cuda_runtime.h>
#include <cstdint>

#define NN   500000
#define EE   4000000
#define FIN  24
#define TSTR 32                     // padded T row stride (floats) = 128B
#define HH   64
#define KC   6
#define OD   6
#define EPSBN 1e-5f
#define NB   ((NN + 1023) / 1024)   // scan blocks = 489

// ---------------- static scratch ----------------
__device__ int    g_deg[NN];
__device__ float  g_dis[NN];
__device__ int    g_rowptr[NN + 1];
__device__ int    g_cur[NN];
__device__ int    g_bsum[NB];
__device__ int    g_boff[NB];
__device__ float2 g_csr[EE];                  // {src_as_bits, weight} sorted by dst
__device__ float  g_T[5][(size_t)NN * TSTR];  // T1..T5, 128B-aligned rows
__device__ float  g_h[(size_t)NN * HH];
__device__ float  g_sum[HH];
__device__ float  g_sumsq[HH];
__device__ float  g_scale[HH];
__device__ float  g_shift[HH];

// ---------------- helpers ----------------
__device__ __forceinline__ unsigned long long pack2(float lo, float hi) {
    unsigned long long r;
    asm("mov.b64 %0, {%1, %2};" : "=l"(r) : "f"(lo), "f"(hi));
    return r;
}
__device__ __forceinline__ void unpack2(unsigned long long v, float& lo, float& hi) {
    asm("mov.b64 {%0, %1}, %2;" : "=f"(lo), "=f"(hi) : "l"(v));
}
__device__ __forceinline__ void ffma2(unsigned long long& d, unsigned long long a,
                                      unsigned long long b) {
    asm("fma.rn.f32x2 %0, %1, %2, %0;" : "+l"(d) : "l"(a), "l"(b));
}

// ---------------- graph preprocessing ----------------
__global__ void k_zero() {
    int i = blockIdx.x * blockDim.x + threadIdx.x;
    if (i < NN) g_deg[i] = 0;
    if (i < HH) { g_sum[i] = 0.f; g_sumsq[i] = 0.f; }
}

__global__ void k_deg(const int4* __restrict__ col4) {
    int i = blockIdx.x * blockDim.x + threadIdx.x;
    if (i >= EE / 4) return;
    int4 c = __ldg(col4 + i);
    atomicAdd(&g_deg[c.x], 1);
    atomicAdd(&g_deg[c.y], 1);
    atomicAdd(&g_deg[c.z], 1);
    atomicAdd(&g_deg[c.w], 1);
}

__global__ void k_dis() {
    int i = blockIdx.x * blockDim.x + threadIdx.x;
    if (i < NN) {
        int d = g_deg[i];
        g_dis[i] = (d > 0) ? rsqrtf((float)d) : 0.f;
    }
}

__global__ __launch_bounds__(1024) void k_scan1() {
    __shared__ int s[1024];
    int tid = threadIdx.x;
    int i = blockIdx.x * 1024 + tid;
    int v = (i < NN) ? g_deg[i] : 0;
    s[tid] = v;
    __syncthreads();
#pragma unroll
    for (int off = 1; off < 1024; off <<= 1) {
        int t = (tid >= off) ? s[tid - off] : 0;
        __syncthreads();
        s[tid] += t;
        __syncthreads();
    }
    if (i < NN) g_rowptr[i] = s[tid] - v;
    if (tid == 1023) g_bsum[blockIdx.x] = s[1023];
}

__global__ __launch_bounds__(512) void k_scan2() {
    __shared__ int s[512];
    int tid = threadIdx.x;
    int v = (tid < NB) ? g_bsum[tid] : 0;
    s[tid] = v;
    __syncthreads();
#pragma unroll
    for (int off = 1; off < 512; off <<= 1) {
        int t = (tid >= off) ? s[tid - off] : 0;
        __syncthreads();
        s[tid] += t;
        __syncthreads();
    }
    if (tid < NB) g_boff[tid] = s[tid] - v;
}

__global__ void k_scan3() {
    int i = blockIdx.x * blockDim.x + threadIdx.x;
    if (i < NN) {
        int rp = g_rowptr[i] + g_boff[i >> 10];
        g_rowptr[i] = rp;
        g_cur[i] = rp;
    }
    if (i == 0) g_rowptr[NN] = EE;
}

__global__ void k_scatter(const int* __restrict__ row, const int* __restrict__ col) {
    int e = blockIdx.x * blockDim.x + threadIdx.x;
    if (e >= EE) return;
    int r = __ldg(row + e);
    int c = __ldg(col + e);
    float w = -g_dis[r] * g_dis[c];
    int pos = atomicAdd(&g_cur[c], 1);
    g_csr[pos] = make_float2(__int_as_float(r), w);
}

// ---------------- propagation: cooperative gather ----------------
// 8 lanes per node (lanes 0-5 active), 4 nodes per warp.
// Lane `sub` owns feature chunk [4*sub, 4*sub+4) across all of node's edges.
// Coalesced gathers (one row = one 128B line when padded), no atomics, no shfl.
__global__ __launch_bounds__(256) void k_gather(int dsti, int prevI, int prev2I,
                                                const float* __restrict__ x,
                                                float scl, int do_sub) {
    int t = blockIdx.x * blockDim.x + threadIdx.x;
    int node = t >> 3;
    if (node >= NN) return;
    int sub = t & 7;
    bool act = sub < 6;

    const float* src = (prevI < 0) ? x : g_T[prevI];
    int sstr = (prevI < 0) ? FIN : TSTR;

    int p  = __ldg(&g_rowptr[node]);
    int p1 = __ldg(&g_rowptr[node + 1]);

    float ax = 0.f, ay = 0.f, az = 0.f, aw = 0.f;

    // unroll-by-2 software pipeline for MLP
    for (; p + 1 < p1; p += 2) {
        float2 e0 = __ldg(&g_csr[p]);
        float2 e1 = __ldg(&g_csr[p + 1]);
        int r0 = __float_as_int(e0.x);
        int r1 = __float_as_int(e1.x);
        if (act) {
            float4 v0 = __ldg((const float4*)(src + (size_t)r0 * sstr) + sub);
            float4 v1 = __ldg((const float4*)(src + (size_t)r1 * sstr) + sub);
            ax += e0.y * v0.x + e1.y * v1.x;
            ay += e0.y * v0.y + e1.y * v1.y;
            az += e0.y * v0.z + e1.y * v1.z;
            aw += e0.y * v0.w + e1.y * v1.w;
        }
    }
    if (p < p1) {
        float2 e0 = __ldg(&g_csr[p]);
        int r0 = __float_as_int(e0.x);
        if (act) {
            float4 v0 = __ldg((const float4*)(src + (size_t)r0 * sstr) + sub);
            ax += e0.y * v0.x;
            ay += e0.y * v0.y;
            az += e0.y * v0.z;
            aw += e0.y * v0.w;
        }
    }

    if (!act) return;
    ax *= scl; ay *= scl; az *= scl; aw *= scl;
    if (do_sub) {
        const float* p2 = (prev2I < 0) ? x : g_T[prev2I];
        int p2str = (prev2I < 0) ? FIN : TSTR;
        float4 q = __ldg((const float4*)(p2 + (size_t)node * p2str) + sub);
        ax -= q.x; ay -= q.y; az -= q.z; aw -= q.w;
    }
    ((float4*)(g_T[dsti] + (size_t)node * TSTR))[sub] = make_float4(ax, ay, az, aw);
}

// ---------------- h = [x|T1..T5] @ W[144,64] + b1 ; + BN stats ----------------
__global__ __launch_bounds__(128) void k_gemm(const float* __restrict__ x,
                                              const float* __restrict__ W1,
                                              const float* __restrict__ b1) {
    __shared__ float sW[KC * FIN * HH];   // 36 KB
    __shared__ float sRs[4][HH];
    __shared__ float sRq[4][HH];

    int tid = threadIdx.x;
    for (int i = tid; i < KC * FIN * HH; i += 128) sW[i] = W1[i];
    __syncthreads();

    int half = tid & 1;
    int n0 = blockIdx.x * 128 + (tid >> 1) * 2;
    int n1 = n0 + 1;
    bool v0 = (n0 < NN), v1 = (n1 < NN);

    unsigned long long acc0[16], acc1[16];
#pragma unroll
    for (int j = 0; j < 16; j++) { acc0[j] = 0ull; acc1[j] = 0ull; }

#pragma unroll
    for (int k = 0; k < KC; k++) {
        const float* base = (k == 0 ? x : g_T[k - 1]);
        int str = (k == 0 ? FIN : TSTR);
        const float4* s40 = (const float4*)(base + (size_t)n0 * str);
        const float4* s41 = (const float4*)(base + (size_t)n1 * str);
#pragma unroll
        for (int i4 = 0; i4 < 6; i4++) {
            float4 a = v0 ? __ldg(s40 + i4) : make_float4(0.f, 0.f, 0.f, 0.f);
            float4 b = v1 ? __ldg(s41 + i4) : make_float4(0.f, 0.f, 0.f, 0.f);
            float av[4] = {a.x, a.y, a.z, a.w};
            float bv[4] = {b.x, b.y, b.z, b.w};
#pragma unroll
            for (int t = 0; t < 4; t++) {
                int i = i4 * 4 + t;
                unsigned long long pa = pack2(av[t], av[t]);
                unsigned long long pb = pack2(bv[t], bv[t]);
                const unsigned long long* wr =
                    (const unsigned long long*)&sW[(k * FIN + i) * HH + half * 32];
#pragma unroll
                for (int j = 0; j < 16; j++) {
                    unsigned long long wj = wr[j];
                    ffma2(acc0[j], pa, wj);
                    ffma2(acc1[j], pb, wj);
                }
            }
        }
    }

    float s[32], q[32];
#pragma unroll
    for (int j = 0; j < 16; j++) {
        float b0 = __ldg(&b1[half * 32 + 2 * j]);
        float b1v = __ldg(&b1[half * 32 + 2 * j + 1]);
        float a0, a1c, c0, c1;
        unpack2(acc0[j], a0, a1c);
        unpack2(acc1[j], c0, c1);
        a0 += b0; a1c += b1v; c0 += b0; c1 += b1v;
        s[2 * j]     = (v0 ? a0 : 0.f) + (v1 ? c0 : 0.f);
        s[2 * j + 1] = (v0 ? a1c : 0.f) + (v1 ? c1 : 0.f);
        q[2 * j]     = (v0 ? a0 * a0 : 0.f) + (v1 ? c0 * c0 : 0.f);
        q[2 * j + 1] = (v0 ? a1c * a1c : 0.f) + (v1 ? c1 * c1 : 0.f);
        if (v0) ((float2*)(g_h + (size_t)n0 * HH + half * 32))[j] = make_float2(a0, a1c);
        if (v1) ((float2*)(g_h + (size_t)n1 * HH + half * 32))[j] = make_float2(c0, c1);
    }

    int lane = tid & 31, wid = tid >> 5;
#pragma unroll
    for (int j = 0; j < 32; j++) {
        float sv = s[j], qv = q[j];
#pragma unroll
        for (int off = 2; off < 32; off <<= 1) {
            sv += __shfl_xor_sync(0xffffffffu, sv, off);
            qv += __shfl_xor_sync(0xffffffffu, qv, off);
        }
        if ((lane >> 1) == 0) {
            sRs[wid][(lane & 1) * 32 + j] = sv;
            sRq[wid][(lane & 1) * 32 + j] = qv;
        }
    }
    __syncthreads();
    if (tid < HH) {
        float a = sRs[0][tid] + sRs[1][tid] + sRs[2][tid] + sRs[3][tid];
        float b = sRq[0][tid] + sRq[1][tid] + sRq[2][tid] + sRq[3][tid];
        atomicAdd(&g_sum[tid], a);
        atomicAdd(&g_sumsq[tid], b);
    }
}

__global__ void k_bnparam(const float* __restrict__ gamma, const float* __restrict__ beta) {
    int j = threadIdx.x;
    if (j < HH) {
        float inv_n = 1.f / (float)NN;
        float mean = g_sum[j] * inv_n;
        float var  = g_sumsq[j] * inv_n - mean * mean;
        float rstd = rsqrtf(var + EPSBN);
        float sc = gamma[j] * rstd;
        g_scale[j] = sc;
        g_shift[j] = beta[j] - mean * sc;
    }
}

__global__ __launch_bounds__(256) void k_final(const float* __restrict__ Wmix,
                                               const float* __restrict__ bmix,
                                               float* __restrict__ out) {
    __shared__ float sWm[HH * OD];
    __shared__ float sSc[HH], sSh[HH], sB[OD];
    int tid = threadIdx.x;
    for (int i = tid; i < HH * OD; i += 256) sWm[i] = Wmix[i];
    if (tid < HH) { sSc[tid] = g_scale[tid]; sSh[tid] = g_shift[tid]; }
    if (tid < OD) sB[tid] = bmix[tid];
    __syncthreads();

    int n = blockIdx.x * 256 + tid;
    if (n >= NN) return;

    float o0 = sB[0], o1 = sB[1], o2 = sB[2], o3 = sB[3], o4 = sB[4], o5 = sB[5];
    const float4* hp = (const float4*)(g_h + (size_t)n * HH);
#pragma unroll
    for (int j4 = 0; j4 < 16; j4++) {
        float4 hv = hp[j4];
        float hv4[4] = {hv.x, hv.y, hv.z, hv.w};
#pragma unroll
        for (int t = 0; t < 4; t++) {
            int j = 4 * j4 + t;
            float val = fmaxf(hv4[t] * sSc[j] + sSh[j], 0.f);
            const float* wm = &sWm[j * OD];
            o0 += val * wm[0]; o1 += val * wm[1]; o2 += val * wm[2];
            o3 += val * wm[3]; o4 += val * wm[4]; o5 += val * wm[5];
        }
    }
    float* op = out + (size_t)n * OD;
    op[0] = o0; op[1] = o1; op[2] = o2; op[3] = o3; op[4] = o4; op[5] = o5;
}

// ---------------- launch ----------------
extern "C" void kernel_launch(void* const* d_in, const int* in_sizes, int n_in,
                              void* d_out, int out_size) {
    const float* x     = (const float*)d_in[0];
    const int*   ei    = (const int*)  d_in[1];
    const float* W1    = (const float*)d_in[2];
    const float* b1    = (const float*)d_in[3];
    const float* gamma = (const float*)d_in[4];
    const float* beta  = (const float*)d_in[5];
    const float* Wmix  = (const float*)d_in[6];
    const float* bmix  = (const float*)d_in[7];
    float* out = (float*)d_out;

    const int* row = ei;
    const int* col = ei + EE;

    const int TB = 256;
    int gN  = (NN + TB - 1) / TB;
    int gE  = (EE + TB - 1) / TB;
    int gE4 = (EE / 4 + TB - 1) / TB;
    int gG  = (8 * NN + TB - 1) / TB;   // 8 lanes per node

    k_zero<<<gN, TB>>>();
    k_deg<<<gE4, TB>>>((const int4*)col);
    k_dis<<<gN, TB>>>();
    k_scan1<<<NB, 1024>>>();
    k_scan2<<<1, 512>>>();
    k_scan3<<<gN, TB>>>();
    k_scatter<<<gE, TB>>>(row, col);

    // T1 = L_hat x
    k_gather<<<gG, TB>>>(0, -1, 0, x, 1.f, 0);
    // T2 = 2 L_hat T1 - x
    k_gather<<<gG, TB>>>(1, 0, -1, x, 2.f, 1);
    // T3 = 2 L_hat T2 - T1
    k_gather<<<gG, TB>>>(2, 1, 0, x, 2.f, 1);
    // T4 = 2 L_hat T3 - T2
    k_gather<<<gG, TB>>>(3, 2, 1, x, 2.f, 1);
    // T5 = 2 L_hat T4 - T3
    k_gather<<<gG, TB>>>(4, 3, 2, x, 2.f, 1);

    k_gemm<<<(NN + 127) / 128, 128>>>(x, W1, b1);
    k_bnparam<<<1, HH>>>(gamma, beta);
    k_final<<<gN, TB>>>(Wmix, bmix, out);
}